// round 17
// baseline (speedup 1.0000x reference)
#include <cuda_runtime.h>
#include <cuda_fp16.h>
#include <stdint.h>

#define NB 4
#define NS 2048
#define ND 1024
#define NH 16
#define NHK 4
#define NHD 64
#define NTOK (NB*NS)

// ---------------- baseline PTX helpers ----------------
__device__ __forceinline__ uint32_t smem_u32(const void* p) {
    uint32_t a;
    asm("{ .reg .u64 t; cvta.to.shared.u64 t, %1; cvt.u32.u64 %0, t; }" : "=r"(a) : "l"(p));
    return a;
}
#define CPA(dst, src) \
    asm volatile("cp.async.cg.shared.global [%0], [%1], 16;" :: "r"(dst), "l"(src))
#define CP_COMMIT asm volatile("cp.async.commit_group;" ::: "memory")
#define CP_WAIT0  asm volatile("cp.async.wait_group 0;" ::: "memory")
#define CP_WAIT1  asm volatile("cp.async.wait_group 1;" ::: "memory")
#define LDSM4(r0,r1,r2,r3,a) \
    asm volatile("ldmatrix.sync.aligned.m8n8.x4.shared.b16 {%0,%1,%2,%3},[%4];" \
        : "=r"(r0),"=r"(r1),"=r"(r2),"=r"(r3) : "r"(a))
#define LDSM4T(r0,r1,r2,r3,a) \
    asm volatile("ldmatrix.sync.aligned.m8n8.x4.trans.shared.b16 {%0,%1,%2,%3},[%4];" \
        : "=r"(r0),"=r"(r1),"=r"(r2),"=r"(r3) : "r"(a))

__device__ __forceinline__ void mma16816(float* c, uint32_t a0, uint32_t a1,
                                         uint32_t a2, uint32_t a3,
                                         uint32_t b0, uint32_t b1) {
    asm volatile(
        "mma.sync.aligned.m16n8k16.row.col.f32.f16.f16.f32 "
        "{%0,%1,%2,%3},{%4,%5,%6,%7},{%8,%9},{%0,%1,%2,%3};"
        : "+f"(c[0]), "+f"(c[1]), "+f"(c[2]), "+f"(c[3])
        : "r"(a0), "r"(a1), "r"(a2), "r"(a3), "r"(b0), "r"(b1));
}

__device__ __forceinline__ uint32_t pack2h(float x, float y) {
    uint32_t r;
    asm("cvt.rn.f16x2.f32 %0, %1, %2;" : "=r"(r) : "f"(y), "f"(x));
    return r;
}
__device__ __forceinline__ uint32_t exp2h2(float x, float y) {
    uint32_t h = pack2h(x, y), r;
    asm("ex2.approx.f16x2 %0, %1;" : "=r"(r) : "r"(h));
    return r;
}
__device__ __forceinline__ uint32_t hadd2u(uint32_t a, uint32_t b) {
    uint32_t r;
    asm("add.f16x2 %0, %1, %2;" : "=r"(r) : "r"(a), "r"(b));
    return r;
}

// ---------------- scratch ----------------
__device__ __align__(256) __half wqth[ND*ND];
__device__ __align__(256) __half wkth[256*ND];
__device__ __align__(256) __half wvth[256*ND];
__device__ __align__(256) __half woth[ND*ND];
__device__ __align__(256) __half qbh[NTOK*ND];             // Q: fp16
__device__ __align__(256) __half kbh[NTOK*256];            // K: fp16
__device__ __align__(256) __half vbh[NTOK*256];            // V: fp16 [tok,256]
__device__ __align__(256) __half aoh[NTOK*ND];             // attn out: fp16

// ---------------- prep: weight transposes ----------------
__global__ void transpose_pack_dual(const float* __restrict__ in0,
                                    const float* __restrict__ in1, int ld,
                                    __half* __restrict__ o0, __half* __restrict__ o1,
                                    int R, int C)
{
    __shared__ float t[32][33];
    const float* ip = blockIdx.z ? in1 : in0;
    __half* oh = blockIdx.z ? o1 : o0;
    const int r0 = blockIdx.y << 5, c0 = blockIdx.x << 5;
    const int tx = threadIdx.x, ty = threadIdx.y;
#pragma unroll
    for (int k = 0; k < 4; k++)
        t[ty + 8*k][tx] = ip[(size_t)(r0 + ty + 8*k) * ld + c0 + tx];
    __syncthreads();
#pragma unroll
    for (int k = 0; k < 4; k++) {
        int oc = ty + 8*k;
        oh[(size_t)(c0 + oc) * R + r0 + tx] = __float2half(t[tx][oc]);
    }
}

// ---------------- GEMM cores (K-chunk 64, 2 CTAs/SM) ----------------
#define G2ST 144u
#define G2TILE 18432u
#define G2STAGE 36864u

// MMA phase shared by both bodies
__device__ __forceinline__ void mma_phase(uint32_t ab, int m0, int n0,
                                          int rowA, int koA, int rB4, int cB4,
                                          float c[4][4][4])
{
    const uint32_t bb = ab + G2TILE;
#pragma unroll
    for (int kk = 0; kk < 4; kk++) {
        uint32_t ah[4][4];
#pragma unroll
        for (int mi = 0; mi < 4; mi++) {
            uint32_t a = ab + (uint32_t)(m0 + mi * 16 + rowA) * G2ST
                           + (uint32_t)(koA + kk * 16) * 2u;
            LDSM4(ah[mi][0], ah[mi][1], ah[mi][2], ah[mi][3], a);
        }
#pragma unroll
        for (int np = 0; np < 2; np++) {
            uint32_t badr = bb + (uint32_t)(n0 + np * 16 + rB4) * G2ST
                              + (uint32_t)(kk * 16 + cB4) * 2u;
            uint32_t bh0, bh1, bh2, bh3;
            LDSM4(bh0, bh1, bh2, bh3, badr);
#pragma unroll
            for (int mi = 0; mi < 4; mi++) {
                mma16816(c[mi][2*np],   ah[mi][0], ah[mi][1], ah[mi][2], ah[mi][3], bh0, bh1);
                mma16816(c[mi][2*np+1], ah[mi][0], ah[mi][1], ah[mi][2], ah[mi][3], bh2, bh3);
            }
        }
    }
}

__device__ __forceinline__ void gemm_epilogue(float c[4][4][4], float* Cf, __half* Ch,
                                              int N, float outScale, int rowBase,
                                              int colBase, int m0, int n0, int l)
{
    const int rq = l >> 2, cq = (l & 3) * 2;
#pragma unroll
    for (int mi = 0; mi < 4; mi++)
#pragma unroll
        for (int ni = 0; ni < 4; ni++)
#pragma unroll
            for (int rv = 0; rv < 2; rv++) {
                int row = rowBase + m0 + mi * 16 + rq + rv * 8;
                int col = colBase + n0 + ni * 8 + cq;
                float x = c[mi][ni][rv * 2]     * outScale;
                float y = c[mi][ni][rv * 2 + 1] * outScale;
                if (Cf) {
                    float2 o; o.x = x; o.y = y;
                    *(float2*)(Cf + (size_t)row * N + col) = o;
                } else {
                    *(uint32_t*)(Ch + (size_t)row * N + col) = pack2h(x, y);
                }
            }
}

// fp16-A body (O projection)
__device__ __forceinline__ void gemm_body(
    const __half* __restrict__ Ah, const __half* __restrict__ Bh,
    float* __restrict__ Cf, __half* __restrict__ Ch,
    int N, int K, float outScale, int rowBase, int colBase, char* sm)
{
    const uint32_t sb = smem_u32(sm);
    const int tid = threadIdx.x, l = tid & 31, wid = tid >> 5;
    const int m0 = (wid >> 2) * 64, n0 = (wid & 3) * 32;
    const int nst = K / 64;

    float c[4][4][4];
#pragma unroll
    for (int a = 0; a < 4; a++)
#pragma unroll
        for (int b = 0; b < 4; b++)
#pragma unroll
            for (int d = 0; d < 4; d++) c[a][b][d] = 0.0f;

    auto load_stage = [&](int s) {
        const uint32_t b0 = sb + (uint32_t)(s & 1) * G2STAGE;
        const int k0 = s * 64;
#pragma unroll
        for (int i = 0; i < 4; i++) {
            const int idx = tid + i * 256;
            const int row = idx >> 3;
            const int ch  = idx & 7;
            const uint32_t dst = b0 + (uint32_t)row * G2ST + (uint32_t)ch * 16u;
            CPA(dst,          Ah + (size_t)(rowBase + row) * K + k0 + ch * 8);
            CPA(dst + G2TILE, Bh + (size_t)(colBase + row) * K + k0 + ch * 8);
        }
    };

    const int rowA = (l & 7) + ((l >> 3) & 1) * 8;
    const int koA  = (l >> 4) * 8;
    const int rB4  = (l & 7) + ((l >> 4) & 1) * 8;
    const int cB4  = ((l >> 3) & 1) * 8;

    load_stage(0); CP_COMMIT;
    for (int s = 0; s < nst; s++) {
        if (s + 1 < nst) { load_stage(s + 1); CP_COMMIT; CP_WAIT1; }
        else CP_WAIT0;
        __syncthreads();
        mma_phase(sb + (uint32_t)(s & 1) * G2STAGE, m0, n0, rowA, koA, rB4, cB4, c);
        __syncthreads();
    }
    gemm_epilogue(c, Cf, Ch, N, outScale, rowBase, colBase, m0, n0, l);
}

// fp32-A body (QKV projections): A loaded fp32 -> cvt.rn -> smem fp16.
// A(s+1) LDG issued before MMA(s); STS at next iter top (latency hidden).
__device__ __forceinline__ void gemm_body_f32(
    const float* __restrict__ Af, const __half* __restrict__ Bh,
    __half* __restrict__ Ch,
    int N, int K, float outScale, int rowBase, int colBase, char* sm)
{
    const uint32_t sb = smem_u32(sm);
    const int tid = threadIdx.x, l = tid & 31, wid = tid >> 5;
    const int m0 = (wid >> 2) * 64, n0 = (wid & 3) * 32;
    const int nst = K / 64;
    const int K4 = K >> 2;

    float c[4][4][4];
#pragma unroll
    for (int a = 0; a < 4; a++)
#pragma unroll
        for (int b = 0; b < 4; b++)
#pragma unroll
            for (int d = 0; d < 4; d++) c[a][b][d] = 0.0f;

    const int arow = tid >> 4;          // 0..15 base row step 16? no: 2048 chunks
    // A tile: 128 rows x 16 float4; thread handles 8 chunks
    // idx = tid + i*256: row = idx>>4 (0..127), c4 = idx&15
    const float4* A4 = (const float4*)Af;

    float4 rf[8];
    auto ldgA = [&](int s) {
        const int k40 = (s * 64) >> 2;
#pragma unroll
        for (int i = 0; i < 8; i++) {
            const int idx = tid + i * 256;
            const int row = idx >> 4, c4 = idx & 15;
            rf[i] = A4[(size_t)(rowBase + row) * K4 + k40 + c4];
        }
    };
    auto stsA = [&](int s) {
        const uint32_t b0 = sb + (uint32_t)(s & 1) * G2STAGE;
#pragma unroll
        for (int i = 0; i < 8; i++) {
            const int idx = tid + i * 256;
            const int row = idx >> 4, c4 = idx & 15;
            uint2 u;
            u.x = pack2h(rf[i].x, rf[i].y);
            u.y = pack2h(rf[i].z, rf[i].w);
            *(uint2*)(sm + (b0 - sb) + (uint32_t)row * G2ST + (uint32_t)c4 * 8u) = u;
        }
    };
    auto cpaB = [&](int s) {
        const uint32_t b0 = sb + (uint32_t)(s & 1) * G2STAGE + G2TILE;
        const int k0 = s * 64;
#pragma unroll
        for (int i = 0; i < 4; i++) {
            const int idx = tid + i * 256;
            const int row = idx >> 3, ch = idx & 7;
            CPA(b0 + (uint32_t)row * G2ST + (uint32_t)ch * 16u,
                Bh + (size_t)(colBase + row) * K + k0 + ch * 8);
        }
    };

    const int rowA = (l & 7) + ((l >> 3) & 1) * 8;
    const int koA  = (l >> 4) * 8;
    const int rB4  = (l & 7) + ((l >> 4) & 1) * 8;
    const int cB4  = ((l >> 3) & 1) * 8;

    ldgA(0);
    cpaB(0); CP_COMMIT;
    for (int s = 0; s < nst; s++) {
        stsA(s);
        if (s + 1 < nst) { ldgA(s + 1); cpaB(s + 1); CP_COMMIT; CP_WAIT1; }
        else CP_WAIT0;
        __syncthreads();
        mma_phase(sb + (uint32_t)(s & 1) * G2STAGE, m0, n0, rowA, koA, rB4, cB4, c);
        __syncthreads();
    }
    gemm_epilogue(c, nullptr, Ch, N, outScale, rowBase, colBase, m0, n0, l);
}

__global__ void __launch_bounds__(256, 2)
gemm_mma(const __half* __restrict__ Ah, const __half* __restrict__ Bh,
         float* __restrict__ Cf, __half* __restrict__ Ch,
         int N, int K, float outScale)
{
    extern __shared__ char sm[];
    gemm_body(Ah, Bh, Cf, Ch, N, K, outScale, blockIdx.y * 128, blockIdx.x * 128, sm);
}

// fused Q/K/V projections, A operands read fp32 directly from inputs
__global__ void __launch_bounds__(256, 2)
gemm_mma_qkv(const float* __restrict__ Aq, const float* __restrict__ Ak,
             const float* __restrict__ Av,
             const __half* __restrict__ Wq, const __half* __restrict__ Wk,
             const __half* __restrict__ Wv,
             __half* __restrict__ Cq, __half* __restrict__ Ck,
             __half* __restrict__ Cv)
{
    extern __shared__ char sm[];
    const int bx = blockIdx.x;
    const int rowBase = blockIdx.y * 128;
    if (bx < 8) {
        gemm_body_f32(Aq, Wq, Cq, ND, ND, 0.18033688f, rowBase, bx * 128, sm);
    } else if (bx < 10) {
        gemm_body_f32(Ak, Wk, Ck, 256, ND, 1.0f, rowBase, (bx - 8) * 128, sm);
    } else {
        gemm_body_f32(Av, Wv, Cv, 256, ND, 1.0f, rowBase, (bx - 10) * 128, sm);
    }
}

// ---------------- fused flash attention (V via trans-ldmatrix) ----------------
#define QST 144u
#define QTILE 18432u
#define KTILE 18432u
#define FSTAGE 36864u          // K tile + V tile (both [128 s][64 d], QST stride)
#define OFF_STAGE 18432u
#define SMEM_FLASH 92160       // 18432 + 2*36864

__global__ void __launch_bounds__(256, 2)
flash_mma(const __half* __restrict__ Qh, const __half* __restrict__ Kh,
          const __half* __restrict__ Vh, __half* __restrict__ Oh)
{
    extern __shared__ char sm[];
    const uint32_t sb = smem_u32(sm);
    const int tid = threadIdx.x, l = tid & 31, wid = tid >> 5;
    const int m0 = wid * 16;
    const int q0 = blockIdx.x * 128, h = blockIdx.y, b = blockIdx.z;
    const int khh = h >> 2;

    const int rowA = (l & 7) + ((l >> 3) & 1) * 8;
    const int koA  = (l >> 4) * 8;
    const int rB4  = (l & 7) + ((l >> 4) & 1) * 8;   // K frags (non-trans)
    const int cB4  = ((l >> 3) & 1) * 8;
    const int rV   = (l & 7) + ((l >> 3) & 1) * 8;   // V frags (trans): s-dim
    const int cV   = ((l >> 4) & 1) * 8;             //                 d-dim
    const int rq   = l >> 2;

    // Q load (group 0)
#pragma unroll
    for (int i = 0; i < 4; i++) {
        int idx = tid + i * 256;
        int row = idx >> 3, ch = idx & 7;
        uint32_t dst = sb + (uint32_t)row * QST + (uint32_t)ch * 16u;
        size_t src = (size_t)(b * NS + q0 + row) * ND + h * 64 + ch * 8;
        CPA(dst, Qh + src);
    }
    CP_COMMIT;

    auto load_kv = [&](int j) {
        const uint32_t ob = sb + OFF_STAGE + (uint32_t)(j & 1) * FSTAGE;
        const int s0 = j * 128;
#pragma unroll
        for (int i = 0; i < 4; i++) {
            int idx = tid + i * 256;
            int row = idx >> 3, ch = idx & 7;
            uint32_t dst = ob + (uint32_t)row * QST + (uint32_t)ch * 16u;
            size_t src = (size_t)(b * NS + s0 + row) * 256 + khh * 64 + ch * 8;
            CPA(dst,         Kh + src);
            CPA(dst + KTILE, Vh + src);
        }
    };
    load_kv(0); CP_COMMIT;

    CP_WAIT1;
    __syncthreads();
    uint32_t qh[4][4];
#pragma unroll
    for (int kk = 0; kk < 4; kk++) {
        uint32_t a = sb + (uint32_t)(m0 + rowA) * QST + (uint32_t)(koA + kk * 16) * 2u;
        LDSM4(qh[kk][0], qh[kk][1], qh[kk][2], qh[kk][3], a);
    }

    float o[8][4];
#pragma unroll
    for (int a = 0; a < 8; a++)
#pragma unroll
        for (int d = 0; d < 4; d++) o[a][d] = 0.0f;
    float lacc[2] = {0.f, 0.f};

    for (int j = 0; j < 16; j++) {
        if (j + 1 < 16) { load_kv(j + 1); CP_COMMIT; CP_WAIT1; }
        else CP_WAIT0;
        __syncthreads();
        const uint32_t kb = sb + OFF_STAGE + (uint32_t)(j & 1) * FSTAGE;
        const uint32_t vb = kb + KTILE;

        uint32_t ph[32];

        // ---- S halves: 64 kv cols at a time; exp2 in f16x2, pre-packed P ----
#pragma unroll
        for (int hf = 0; hf < 2; hf++) {
            float s[8][4];
#pragma unroll
            for (int a = 0; a < 8; a++)
#pragma unroll
                for (int d = 0; d < 4; d++) s[a][d] = 0.0f;

#pragma unroll
            for (int kk = 0; kk < 4; kk++) {
#pragma unroll
                for (int t = 0; t < 4; t++) {
                    int n2 = hf * 4 + t;
                    uint32_t badr = kb + (uint32_t)(n2 * 16 + rB4) * QST
                                      + (uint32_t)(kk * 16 + cB4) * 2u;
                    uint32_t bh0, bh1, bh2, bh3;
                    LDSM4(bh0, bh1, bh2, bh3, badr);
                    mma16816(s[2*t],   qh[kk][0], qh[kk][1], qh[kk][2], qh[kk][3], bh0, bh1);
                    mma16816(s[2*t+1], qh[kk][0], qh[kk][1], qh[kk][2], qh[kk][3], bh2, bh3);
                }
            }
#pragma unroll
            for (int a = 0; a < 8; a++) {
                int g = 8 * hf + a;
                ph[2*g]   = exp2h2(s[a][0], s[a][1]);
                ph[2*g+1] = exp2h2(s[a][2], s[a][3]);
            }
        }

        // ---- row sums: HADD2 tree ----
        {
            uint32_t se = ph[0], so = ph[1];
#pragma unroll
            for (int g = 1; g < 16; g++) {
                se = hadd2u(se, ph[2*g]);
                so = hadd2u(so, ph[2*g+1]);
            }
            __half2 e2 = *(__half2*)&se, o2 = *(__half2*)&so;
            float ps[2];
            ps[0] = __half2float(e2.x) + __half2float(e2.y);
            ps[1] = __half2float(o2.x) + __half2float(o2.y);
#pragma unroll
            for (int rv = 0; rv < 2; rv++) {
                ps[rv] += __shfl_xor_sync(0xffffffffu, ps[rv], 1);
                ps[rv] += __shfl_xor_sync(0xffffffffu, ps[rv], 2);
                lacc[rv] += ps[rv];
            }
        }

        // ---- O += P @ V: V tile [s][d], B-frags via trans ldmatrix ----
#pragma unroll
        for (int kk = 0; kk < 8; kk++) {
#pragma unroll
            for (int n2 = 0; n2 < 4; n2++) {
                uint32_t va = vb + (uint32_t)(kk * 16 + rV) * QST
                                 + (uint32_t)(n2 * 16 + cV) * 2u;
                uint32_t vh0, vh1, vh2, vh3;
                LDSM4T(vh0, vh1, vh2, vh3, va);
                mma16816(o[2*n2],   ph[4*kk], ph[4*kk+1], ph[4*kk+2], ph[4*kk+3], vh0, vh1);
                mma16816(o[2*n2+1], ph[4*kk], ph[4*kk+1], ph[4*kk+2], ph[4*kk+3], vh2, vh3);
            }
        }
        __syncthreads();
    }

    // epilogue
#pragma unroll
    for (int rv = 0; rv < 2; rv++) {
        float inv = 1.0f / lacc[rv];
        int rowl = m0 + rq + rv * 8;
        size_t gbase = (size_t)(b * NS + q0 + rowl) * ND + h * 64 + (l & 3) * 2;
#pragma unroll
        for (int nd = 0; nd < 8; nd++) {
            float x = o[nd][rv * 2]     * inv;
            float y = o[nd][rv * 2 + 1] * inv;
            *(uint32_t*)(Oh + gbase + nd * 8) = pack2h(x, y);
        }
    }
}

// ---------------- launch ----------------
extern "C" void kernel_launch(void* const* d_in, const int* in_sizes, int n_in,
                              void* d_out, int out_size)
{
    const float* query = (const float*)d_in[0];
    const float* key   = (const float*)d_in[1];
    const float* value = (const float*)d_in[2];
    const float* Wq    = (const float*)d_in[3];
    const float* Wk    = (const float*)d_in[4];
    const float* Wv    = (const float*)d_in[5];
    const float* Wo    = (const float*)d_in[6];
    float* out = (float*)d_out;

    __half *p_wqh, *p_wkh, *p_wvh, *p_woh;
    __half *p_qh, *p_kh, *p_vh, *p_aoh;
    cudaGetSymbolAddress((void**)&p_wqh, wqth);
    cudaGetSymbolAddress((void**)&p_wkh, wkth);
    cudaGetSymbolAddress((void**)&p_wvh, wvth);
    cudaGetSymbolAddress((void**)&p_woh, woth);
    cudaGetSymbolAddress((void**)&p_qh, qbh);
    cudaGetSymbolAddress((void**)&p_kh, kbh);
    cudaGetSymbolAddress((void**)&p_vh, vbh);
    cudaGetSymbolAddress((void**)&p_aoh, aoh);

    const int smemG = 2 * (int)G2STAGE;    // 73728
    cudaFuncSetAttribute(gemm_mma, cudaFuncAttributeMaxDynamicSharedMemorySize, smemG);
    cudaFuncSetAttribute(gemm_mma_qkv, cudaFuncAttributeMaxDynamicSharedMemorySize, smemG);
    cudaFuncSetAttribute(flash_mma, cudaFuncAttributeMaxDynamicSharedMemorySize, SMEM_FLASH);

    dim3 tt(32, 8);
    transpose_pack_dual<<<dim3(32, 32, 2), tt>>>(Wq, Wo, ND, p_wqh, p_woh, ND, ND);
    transpose_pack_dual<<<dim3(8,  32, 2), tt>>>(Wk, Wv, 256, p_wkh, p_wvh, ND, 256);

    // fused Q/K/V projections, fp32 A operands (no pack kernel)
    gemm_mma_qkv<<<dim3(12, 64), 256, smemG>>>(query, key, value,
                                               p_wqh, p_wkh, p_wvh,
                                               p_qh, p_kh, p_vh);

    flash_mma<<<dim3(16, NH, NB), 256, SMEM_FLASH>>>(p_qh, p_kh, p_vh, p_aoh);

    // O projection -> fp32 out
    gemm_mma<<<dim3(8, 64), 256, smemG>>>(p_aoh, p_woh, out, nullptr,
                                          ND, ND, 1.0f);
}